// round 11
// baseline (speedup 1.0000x reference)
#include <cuda_runtime.h>
#include <math_constants.h>

// Problem constants (fixed by reference)
constexpr int B = 8;
constexpr int N = 4096;          // == M

// z-strip sort grid
constexpr int   S    = 200;
constexpr float ZLO  = -5.0f;
constexpr float INVW = 20.0f;

constexpr int CHK    = 32;               // target chunks per cloud
constexpr int CSZ    = N / CHK;          // 128 points per chunk
constexpr int QT     = 128;              // threads per search block (4 warps)
constexpr int QBLK   = N / QT;           // 32 query blocks per (pass,b)
constexpr int TOTALB = QBLK * B * 2;     // 512 search blocks

// Scratch (no allocations allowed)
// g_pts[c][b][i] = (-2x, -2y, -2z, x^2+y^2+z^2), z-sorted (strip granularity)
__device__ float4   g_pts[2][B][N];
// g_cb[c][b][k] = (zmin_k, zmax_k, lbound_k = min zmin[k..], ubound_k = max zmax[..k])
__device__ float4   g_cb[2][B][CHK];
__device__ float    g_acc[4];            // rowmin-sum, sqrt-sum, colmin-sum, unc-sum
__device__ unsigned g_tick;

// ---------------------------------------------------------------------------
// Bucket kernel: grid (2, B), block 256. Strip histogram + scatter (z-sort at
// strip granularity), then per-chunk z bounds + monotone prefix/suffix bounds.
// ---------------------------------------------------------------------------
__global__ void __launch_bounds__(256)
bucket_kernel(const float* __restrict__ pred, const float* __restrict__ targ)
{
    __shared__ int   cnt[S];
    __shared__ int   start[S];
    __shared__ int   cur[S];
    __shared__ float czmin[CHK], czmax[CHK];
    const int c = blockIdx.x, b = blockIdx.y, tid = threadIdx.x;
    const float* src = (c == 0 ? pred : targ) + (size_t)b * N * 3;

    if (c == 0 && b == 0) {
        if (tid < 4) g_acc[tid] = 0.f;
        if (tid == 4) g_tick = 0u;
    }

    for (int s = tid; s < S; s += 256) { cnt[s] = 0; cur[s] = 0; }
    __syncthreads();

    for (int i = tid; i < N; i += 256) {
        const float z = src[i * 3 + 2];
        const int s = min(max((int)((z - ZLO) * INVW), 0), S - 1);
        atomicAdd(&cnt[s], 1);
    }
    __syncthreads();

    if (tid == 0) {
        int acc = 0;
        for (int s = 0; s < S; s++) { start[s] = acc; acc += cnt[s]; }
    }
    __syncthreads();

    for (int i = tid; i < N; i += 256) {
        const float x = src[i * 3 + 0];
        const float y = src[i * 3 + 1];
        const float z = src[i * 3 + 2];
        const int s = min(max((int)((z - ZLO) * INVW), 0), S - 1);
        const int pos = start[s] + atomicAdd(&cur[s], 1);
        g_pts[c][b][pos] = make_float4(-2.f * x, -2.f * y, -2.f * z,
                                       x * x + y * y + z * z);
    }
    __syncthreads();

    // per-chunk z min/max: 8 warps x 4 chunks, 4 points per lane
    {
        const int w = tid >> 5, lane = tid & 31;
        for (int q = 0; q < 4; q++) {
            const int ch = w * 4 + q;
            float zmn = CUDART_INF_F, zmx = -CUDART_INF_F;
#pragma unroll
            for (int i = 0; i < 4; i++) {
                const float z = -0.5f * g_pts[c][b][ch * CSZ + lane + 32 * i].z;
                zmn = fminf(zmn, z);
                zmx = fmaxf(zmx, z);
            }
#pragma unroll
            for (int o = 16; o > 0; o >>= 1) {
                zmn = fminf(zmn, __shfl_down_sync(0xffffffffu, zmn, o));
                zmx = fmaxf(zmx, __shfl_down_sync(0xffffffffu, zmx, o));
            }
            if (lane == 0) { czmin[ch] = zmn; czmax[ch] = zmx; }
        }
    }
    __syncthreads();

    if (tid == 0) {                       // monotone bounds (exactness guard)
        float ub = -CUDART_INF_F;
        float lb[CHK + 1];
        lb[CHK] = CUDART_INF_F;
        for (int k = CHK - 1; k >= 0; k--) lb[k] = fminf(lb[k + 1], czmin[k]);
        for (int k = 0; k < CHK; k++) {
            ub = fmaxf(ub, czmax[k]);
            g_cb[c][b][k] = make_float4(czmin[k], czmax[k], lb[k], ub);
        }
    }
}

// ---------------------------------------------------------------------------
// Search kernel: grid (QBLK, B, 2), block 128 (4 autonomous warps).
// Each warp owns 32 z-adjacent queries. Warp-UNIFORM outward chunk walk:
// scan chunk h+-k iff ANY lane's true-bound gap check passes (__any_sync),
// exit when ALL lanes' monotone-bound done predicate holds (__all_sync).
// Every scan is a fully converged dense loop over 128 broadcast target
// points (L1-resident). No barriers, no divergent scans -> exact + fast.
// ---------------------------------------------------------------------------
__global__ void __launch_bounds__(QT)
search_kernel(const float* __restrict__ unc, float* __restrict__ out)
{
    __shared__ float4 sb[CHK];           // (zmin, zmax, lbound, ubound)

    const int tid  = threadIdx.x;
    const int lane = tid & 31;
    const int b    = blockIdx.y;
    const int pass = blockIdx.z;
    const int qc   = pass, tc = 1 - pass;
    const int qi   = blockIdx.x * QT + tid;   // sorted-order query index

    const float4* __restrict__ T = g_pts[tc][b];

    if (tid < CHK) sb[tid] = g_cb[tc][b][tid];

    const float4 Q  = g_pts[qc][b][qi];
    const float qx  = -0.5f * Q.x;
    const float qy  = -0.5f * Q.y;
    const float qz  = -0.5f * Q.z;
    const float qn2 = Q.w;
    __syncthreads();                      // sb ready (only barrier)

    // warp-uniform home chunk from lane 16's z
    const float qzc = __shfl_sync(0xffffffffu, qz, 16);
    int h = 0;
#pragma unroll
    for (int k = 1; k < CHK; k++) if (sb[k].x <= qzc) h = k;

    float best  = CUDART_INF_F;           // partial: min(t^2 - 2 q.t)
    float btrue = CUDART_INF_F;

    auto scan_chunk = [&](int ch) {       // converged dense scan, ILP=4
        const float4* p = T + ch * CSZ;
        float b0 = CUDART_INF_F, b1 = b0, b2 = b0, b3 = b0;
#pragma unroll 2
        for (int j = 0; j < CSZ; j += 4) {
            const float4 t0 = __ldg(p + j),     t1 = __ldg(p + j + 1);
            const float4 t2 = __ldg(p + j + 2), t3 = __ldg(p + j + 3);
            float d0 = fmaf(qz, t0.z, t0.w);
            float d1 = fmaf(qz, t1.z, t1.w);
            float d2 = fmaf(qz, t2.z, t2.w);
            float d3 = fmaf(qz, t3.z, t3.w);
            d0 = fmaf(qy, t0.y, d0);  d1 = fmaf(qy, t1.y, d1);
            d2 = fmaf(qy, t2.y, d2);  d3 = fmaf(qy, t3.y, d3);
            d0 = fmaf(qx, t0.x, d0);  d1 = fmaf(qx, t1.x, d1);
            d2 = fmaf(qx, t2.x, d2);  d3 = fmaf(qx, t3.x, d3);
            b0 = fminf(b0, d0);  b1 = fminf(b1, d1);
            b2 = fminf(b2, d2);  b3 = fminf(b3, d3);
        }
        best  = fminf(best, fminf(fminf(b0, b1), fminf(b2, b3)));
        btrue = qn2 + best;
    };

    scan_chunk(h);                        // home chunk: unconditional

    for (int k = 1; k < CHK; k++) {
        const int chi = h + k, clo = h - k;
        if (chi < CHK) {
            const float g = fmaxf(fmaxf(sb[chi].x - qz, qz - sb[chi].y), 0.f);
            if (__any_sync(0xffffffffu, g * g < btrue)) scan_chunk(chi);
        }
        if (clo >= 0) {
            const float g = fmaxf(fmaxf(sb[clo].x - qz, qz - sb[clo].y), 0.f);
            if (__any_sync(0xffffffffu, g * g < btrue)) scan_chunk(clo);
        }
        // per-lane termination via monotone bounds (conservative, exact)
        const int nlo = h - k - 1, nhi = h + k + 1;
        const float glo = (nlo >= 0)
            ? fmaxf(qz - sb[nlo].w, 0.f) : CUDART_INF_F;   // ubound
        const float ghi = (nhi < CHK)
            ? fmaxf(sb[nhi].z - qz, 0.f) : CUDART_INF_F;   // lbound
        const bool done = (glo * glo >= btrue) && (ghi * ghi >= btrue);
        if (__all_sync(0xffffffffu, done)) break;
    }

    const float d2 = qn2 + best;          // exact min squared distance

    float v0 = 0.f, v1 = 0.f, v2 = 0.f, v3 = 0.f;
    if (pass == 0) {
        v0 = d2;                          // chamfer row term
        v1 = sqrtf(fmaxf(d2, 0.f));       // EMD term
        v3 = unc[b * N + qi];             // uncertainty (order-free sum)
    } else {
        v2 = d2;                          // chamfer col term
    }

#pragma unroll
    for (int o = 16; o > 0; o >>= 1) {
        v0 += __shfl_down_sync(0xffffffffu, v0, o);
        v1 += __shfl_down_sync(0xffffffffu, v1, o);
        v2 += __shfl_down_sync(0xffffffffu, v2, o);
        v3 += __shfl_down_sync(0xffffffffu, v3, o);
    }
    __shared__ float red[4][QT / 32];
    if (lane == 0) {
        const int w = tid >> 5;
        red[0][w] = v0; red[1][w] = v1; red[2][w] = v2; red[3][w] = v3;
    }
    __syncthreads();

    if (tid == 0) {
        float a0 = 0.f, a1 = 0.f, a2 = 0.f, a3 = 0.f;
#pragma unroll
        for (int w = 0; w < QT / 32; w++) {
            a0 += red[0][w]; a1 += red[1][w]; a2 += red[2][w]; a3 += red[3][w];
        }
        atomicAdd(&g_acc[0], a0);
        atomicAdd(&g_acc[1], a1);
        atomicAdd(&g_acc[2], a2);
        atomicAdd(&g_acc[3], a3);

        __threadfence();
        const unsigned t = atomicAdd(&g_tick, 1u);
        if (t == (unsigned)(TOTALB - 1)) {    // last block finalizes
            __threadfence();
            const float inv = 1.0f / (float)(B * N);
            const float chamfer = (g_acc[0] + g_acc[2]) * inv;
            const float emd     = g_acc[1] * inv;
            const float u       = g_acc[3] * inv;
            out[0] = chamfer * 1.0f + emd * 0.5f + u * 0.01f;
            g_tick = 0u;                      // reset for next graph replay
        }
    }
}

// ---------------------------------------------------------------------------
extern "C" void kernel_launch(void* const* d_in, const int* in_sizes, int n_in,
                              void* d_out, int out_size)
{
    const float* pred = (const float*)d_in[0];   // [B, N, 3]
    const float* targ = (const float*)d_in[1];   // [B, M, 3]
    const float* unc  = (const float*)d_in[2];   // [B, N]
    float* out = (float*)d_out;

    dim3 bgrid(2, B);                            // 16 blocks
    bucket_kernel<<<bgrid, 256>>>(pred, targ);

    dim3 sgrid(QBLK, B, 2);                      // 512 blocks x 128
    search_kernel<<<sgrid, QT>>>(unc, out);
}

// round 13
// speedup vs baseline: 3.4806x; 3.4806x over previous
#include <cuda_runtime.h>
#include <math_constants.h>

constexpr int B = 8;
constexpr int N = 4096;              // == M

// z-strip sort grid
constexpr int   S    = 200;
constexpr float ZLO  = -5.0f;
constexpr float INVW = 20.0f;

constexpr int SPLIT  = 16;           // target chunks
constexpr int CSZ    = N / SPLIT;    // 256 targets per chunk
constexpr int GROUPS = 32;           // query groups per (pass,b)
constexpr int GSZ    = N / GROUPS;   // 128 queries per group (1 warp)
constexpr int SEEDW  = 256;          // seed window (targets) per group

constexpr int THREADS = 128;         // main block (4 warps)
constexpr int R       = 4;
constexpr int TN      = THREADS * R; // 512 queries per tile
constexpr int NTILES  = N / TN;      // 8
constexpr int NSLOT   = SPLIT + 1;   // 16 chunk slots + 1 seed slot

constexpr int TOTALB      = SPLIT * NTILES * 2 * B;  // 2048 main CTAs
constexpr int REDUCERS    = 128;
constexpr int PTS_PER_RED = (B * N) / REDUCERS;      // 256

// Scratch (no device allocations allowed)
__device__ float4   g_pts[2][B][N];          // (-2x,-2y,-2z, x2+y2+z2), z-sorted
__device__ float2   g_cz[2][B][SPLIT];       // chunk (zmin, zmax)
__device__ float    g_part[2][B][NSLOT][N];  // partial mins per slot
__device__ float    g_ub2[2][B][GROUPS];     // per-group NN upper bound^2
__device__ float    g_acc[4];                // rowsum, sqrtsum, colsum, uncsum
__device__ unsigned g_count  = 0;            // main-CTA ticket
__device__ unsigned g_count2 = 0;            // reducer ticket

// ---------------------------------------------------------------------------
// bucket: strip z-sort (scatter transformed points) + exact chunk z bounds.
// ---------------------------------------------------------------------------
__global__ void __launch_bounds__(256)
bucket_kernel(const float* __restrict__ pred, const float* __restrict__ targ)
{
    __shared__ int cnt[S], start[S], cur[S];
    const int c = blockIdx.x, b = blockIdx.y, tid = threadIdx.x;
    const float* src = (c == 0 ? pred : targ) + (size_t)b * N * 3;

    if (c == 0 && b == 0 && tid < 4) g_acc[tid] = 0.f;

    for (int s = tid; s < S; s += 256) { cnt[s] = 0; cur[s] = 0; }
    __syncthreads();
    for (int i = tid; i < N; i += 256) {
        const float z = src[i * 3 + 2];
        const int s = min(max((int)((z - ZLO) * INVW), 0), S - 1);
        atomicAdd(&cnt[s], 1);
    }
    __syncthreads();
    if (tid == 0) {
        int acc = 0;
        for (int s = 0; s < S; s++) { start[s] = acc; acc += cnt[s]; }
    }
    __syncthreads();
    for (int i = tid; i < N; i += 256) {
        const float x = src[i * 3 + 0], y = src[i * 3 + 1], z = src[i * 3 + 2];
        const int s = min(max((int)((z - ZLO) * INVW), 0), S - 1);
        const int pos = start[s] + atomicAdd(&cur[s], 1);
        g_pts[c][b][pos] = make_float4(-2.f * x, -2.f * y, -2.f * z,
                                       x * x + y * y + z * z);
    }
    __syncthreads();

    // exact chunk z ranges: 8 warps x 2 chunks, 8 points per lane
    const int w = tid >> 5, lane = tid & 31;
    for (int q = 0; q < 2; q++) {
        const int ch = w * 2 + q;
        float zmn = CUDART_INF_F, zmx = -CUDART_INF_F;
#pragma unroll
        for (int i = 0; i < 8; i++) {
            const float z = -0.5f * g_pts[c][b][ch * CSZ + lane + 32 * i].z;
            zmn = fminf(zmn, z);
            zmx = fmaxf(zmx, z);
        }
#pragma unroll
        for (int o = 16; o > 0; o >>= 1) {
            zmn = fminf(zmn, __shfl_down_sync(0xffffffffu, zmn, o));
            zmx = fmaxf(zmx, __shfl_down_sync(0xffffffffu, zmx, o));
        }
        if (lane == 0) g_cz[c][b][ch] = make_float2(zmn, zmx);
    }
}

// ---------------------------------------------------------------------------
// seed: per 128-query group, dense scan of 256 index-adjacent (z-near)
// targets -> exact per-query upper bound (slot 16), per-group UB^2 = max,
// slot 0..15 init to +inf, unc partial sum (pass 0 only).
// ---------------------------------------------------------------------------
__global__ void __launch_bounds__(GSZ)
seed_kernel(const float* __restrict__ unc)
{
    __shared__ float4 st[SEEDW];
    __shared__ float  smax[GSZ / 32];

    const int g = blockIdx.x, b = blockIdx.y, pass = blockIdx.z;
    const int tid = threadIdx.x, lane = tid & 31, w = tid >> 5;
    const int qc = pass, tc = 1 - pass;
    const int i0 = g * GSZ;
    const int wlo = min(max(i0 - 64, 0), N - SEEDW);

    st[tid]       = g_pts[tc][b][wlo + tid];
    st[tid + GSZ] = g_pts[tc][b][wlo + tid + GSZ];

    const float4 Q  = g_pts[qc][b][i0 + tid];
    const float qx  = -0.5f * Q.x, qy = -0.5f * Q.y, qz = -0.5f * Q.z;
    const float qn2 = Q.w;
    __syncthreads();

    float b0 = CUDART_INF_F, b1 = CUDART_INF_F;
#pragma unroll 4
    for (int j = 0; j < SEEDW; j += 2) {
        const float4 t0 = st[j], t1 = st[j + 1];
        float d0 = fmaf(qz, t0.z, t0.w);
        float d1 = fmaf(qz, t1.z, t1.w);
        d0 = fmaf(qy, t0.y, d0);  d1 = fmaf(qy, t1.y, d1);
        d0 = fmaf(qx, t0.x, d0);  d1 = fmaf(qx, t1.x, d1);
        b0 = fminf(b0, d0);       b1 = fminf(b1, d1);
    }
    const float d2 = qn2 + fminf(b0, b1);        // true squared dist bound

    float* base = &g_part[pass][b][0][i0 + tid]; // slot stride = N
#pragma unroll
    for (int s = 0; s < SPLIT; s++) base[s * N] = CUDART_INF_F;
    base[SPLIT * N] = d2;                        // slot 16 = seed min

    // group UB^2 = max over 128 queries
    float mx = d2;
#pragma unroll
    for (int o = 16; o > 0; o >>= 1)
        mx = fmaxf(mx, __shfl_down_sync(0xffffffffu, mx, o));
    if (lane == 0) smax[w] = mx;
    __syncthreads();
    if (tid == 0)
        g_ub2[pass][b][g] = fmaxf(fmaxf(smax[0], smax[1]),
                                  fmaxf(smax[2], smax[3]));

    if (pass == 0) {                             // unc sum (order-free)
        float u = unc[b * N + i0 + tid];
#pragma unroll
        for (int o = 16; o > 0; o >>= 1)
            u += __shfl_down_sync(0xffffffffu, u, o);
        if (lane == 0) atomicAdd(&g_acc[3], u);
    }
}

// ---------------------------------------------------------------------------
// main: R6 dense shape (16 chunks x 8 tiles x 2B CTAs, 128 thr, R=4) with
// per-WARP chunk skip: warp owns 128 consecutive sorted queries; skips its
// scan iff gap(group z-range, chunk z-range)^2 >= UB^2(group). Survivors run
// the proven dense smem loop. Fused ticket reduce + finalize.
// ---------------------------------------------------------------------------
__global__ void __launch_bounds__(THREADS)
main_kernel(float* __restrict__ out)
{
    __shared__ float4 sc[CSZ];
    __shared__ int    s_skip;
    __shared__ unsigned s_ticket;
    __shared__ float  red[4][THREADS / 32];

    const int tid  = threadIdx.x, lane = tid & 31, w = tid >> 5;
    const int split = blockIdx.x, ntile = blockIdx.y, zz = blockIdx.z;
    const int b = zz & (B - 1), pass = zz >> 3;
    const int tc = 1 - pass;
    const int group = ntile * 4 + w;
    const int qbase = ntile * TN + w * GSZ + lane;

    const float4* __restrict__ T = g_pts[tc][b];

    if (tid == 0) s_skip = 0;

    // load 4 consecutive-strided queries (group-coherent)
    float px[R], py[R], pz[R], pn2[R], r[R];
    float zmn = CUDART_INF_F, zmx = -CUDART_INF_F;
#pragma unroll
    for (int j = 0; j < R; j++) {
        const float4 Q = g_pts[pass][b][qbase + 32 * j];
        px[j] = -0.5f * Q.x; py[j] = -0.5f * Q.y; pz[j] = -0.5f * Q.z;
        pn2[j] = Q.w;  r[j] = CUDART_INF_F;
        zmn = fminf(zmn, pz[j]);  zmx = fmaxf(zmx, pz[j]);
    }
#pragma unroll
    for (int o = 16; o > 0; o >>= 1) {           // warp z-range (all lanes)
        zmn = fminf(zmn, __shfl_xor_sync(0xffffffffu, zmn, o));
        zmx = fmaxf(zmx, __shfl_xor_sync(0xffffffffu, zmx, o));
    }

    const float2 cz  = g_cz[tc][b][split];
    const float  gap = fmaxf(fmaxf(cz.x - zmx, zmn - cz.y), 0.f);
    const bool   skip = (gap * gap >= g_ub2[pass][b][group]);

    __syncthreads();
    if (lane == 0 && skip) atomicAdd(&s_skip, 1);
    __syncthreads();

    if (s_skip < 4) {                            // some warp needs this chunk
        sc[tid]           = T[split * CSZ + tid];
        sc[tid + THREADS] = T[split * CSZ + tid + THREADS];
        __syncthreads();

        if (!skip) {
#pragma unroll 4
            for (int k = 0; k < CSZ; k++) {
                const float4 v = sc[k];
#pragma unroll
                for (int j = 0; j < R; j++) {
                    float d = fmaf(pz[j], v.z, v.w);
                    d = fmaf(py[j], v.y, d);
                    d = fmaf(px[j], v.x, d);
                    r[j] = fminf(r[j], d);
                }
            }
            float* o = &g_part[pass][b][split][0];
#pragma unroll
            for (int j = 0; j < R; j++)
                o[qbase + 32 * j] = pn2[j] + r[j];
        }
    }

    // ---- ticket: last REDUCERS finishers reduce + finalize ----
    __threadfence();
    __syncthreads();
    if (tid == 0) s_ticket = atomicAdd(&g_count, 1u);
    __syncthreads();
    const unsigned my = s_ticket;
    if (my < (unsigned)(TOTALB - REDUCERS)) return;

    if (tid == 0) {
        while (*((volatile unsigned*)&g_count) < (unsigned)TOTALB)
            __nanosleep(64);
    }
    __syncthreads();
    __threadfence();

    const int rid  = (int)my - (TOTALB - REDUCERS);
    const int base = rid * PTS_PER_RED;

    float s_row = 0.f, s_sqrt = 0.f, s_col = 0.f;
#pragma unroll
    for (int it = 0; it < PTS_PER_RED / THREADS; it++) {
        const int idx = base + it * THREADS + tid;
        const int bb = idx >> 12, nn = idx & (N - 1);

        const float* p = &g_part[0][bb][0][nn];
        float m = p[0];
#pragma unroll
        for (int s = 1; s < NSLOT; s++) m = fminf(m, __ldg(p + (size_t)s * N));
        s_row  += m;
        s_sqrt += sqrtf(fmaxf(m, 0.f));

        const float* q = &g_part[1][bb][0][nn];
        float mc = q[0];
#pragma unroll
        for (int s = 1; s < NSLOT; s++) mc = fminf(mc, __ldg(q + (size_t)s * N));
        s_col += mc;
    }
#pragma unroll
    for (int o = 16; o > 0; o >>= 1) {
        s_row  += __shfl_down_sync(0xffffffffu, s_row,  o);
        s_sqrt += __shfl_down_sync(0xffffffffu, s_sqrt, o);
        s_col  += __shfl_down_sync(0xffffffffu, s_col,  o);
    }
    if (lane == 0) {
        red[0][w] = s_row; red[1][w] = s_sqrt; red[2][w] = s_col;
    }
    __syncthreads();
    if (tid == 0) {
        float a0 = 0.f, a1 = 0.f, a2 = 0.f;
#pragma unroll
        for (int ww = 0; ww < THREADS / 32; ww++) {
            a0 += red[0][ww]; a1 += red[1][ww]; a2 += red[2][ww];
        }
        atomicAdd(&g_acc[0], a0);
        atomicAdd(&g_acc[1], a1);
        atomicAdd(&g_acc[2], a2);

        __threadfence();
        const unsigned done = atomicAdd(&g_count2, 1u);
        if (done == (unsigned)(REDUCERS - 1)) {
            const float inv = 1.0f / (float)(B * N);
            const float chamfer = (g_acc[0] + g_acc[2]) * inv;
            const float emd     = g_acc[1] * inv;
            const float u       = g_acc[3] * inv;
            out[0] = chamfer * 1.0f + emd * 0.5f + u * 0.01f;
            g_count  = 0;                       // reset for graph replay
            g_count2 = 0;
        }
    }
}

// ---------------------------------------------------------------------------
extern "C" void kernel_launch(void* const* d_in, const int* in_sizes, int n_in,
                              void* d_out, int out_size)
{
    const float* pred = (const float*)d_in[0];   // [B, N, 3]
    const float* targ = (const float*)d_in[1];   // [B, M, 3]
    const float* unc  = (const float*)d_in[2];   // [B, N]
    float* out = (float*)d_out;

    dim3 bgrid(2, B);                            // 16 blocks
    bucket_kernel<<<bgrid, 256>>>(pred, targ);

    dim3 sgrid(GROUPS, B, 2);                    // 512 blocks x 128
    seed_kernel<<<sgrid, GSZ>>>(unc);

    dim3 mgrid(SPLIT, NTILES, 2 * B);            // 2048 blocks x 128
    main_kernel<<<mgrid, THREADS>>>(out);
}

// round 14
// speedup vs baseline: 3.9656x; 1.1393x over previous
#include <cuda_runtime.h>
#include <math_constants.h>

constexpr int B = 8;
constexpr int N = 4096;              // == M

// z-strip sort grid
constexpr int   S    = 200;
constexpr float ZLO  = -5.0f;
constexpr float INVW = 20.0f;

constexpr int SPLIT  = 32;           // target chunks
constexpr int CSZ    = N / SPLIT;    // 128 targets per chunk
constexpr int GROUPS = 32;           // query groups per (pass,b)
constexpr int GSZ    = N / GROUPS;   // 128 queries per group (1 warp in main)
constexpr int SEEDW  = 256;          // seed window (targets) per group

constexpr int THREADS = 128;         // main block (4 warps)
constexpr int R       = 4;
constexpr int TN      = THREADS * R; // 512 queries per tile
constexpr int NTILES  = N / TN;      // 8

constexpr int TOTALB      = SPLIT * NTILES * 2 * B;  // 4096 main CTAs
constexpr int REDUCERS    = 128;
constexpr int PTS_PER_RED = (B * N) / REDUCERS;      // 256

// Scratch (no device allocations allowed)
__device__ float4   g_pts[2][B][N];        // (-2x,-2y,-2z, x2+y2+z2), z-sorted
__device__ float2   g_cz[2][B][SPLIT];     // chunk (zmin, zmax)
__device__ unsigned g_best[2][B][N];       // best d2 as uint bits (>=0 floats)
__device__ float    g_ub2[2][B][GROUPS];   // per-group NN upper bound^2
__device__ float    g_acc[4];              // rowsum, sqrtsum, colsum, uncsum
__device__ unsigned g_count  = 0;          // main-CTA ticket
__device__ unsigned g_count2 = 0;          // reducer ticket

// ---------------------------------------------------------------------------
// bucket: strip z-sort (scatter transformed points) + exact chunk z bounds.
// Parallel Hillis-Steele scan replaces the serial 200-strip prefix.
// ---------------------------------------------------------------------------
__global__ void __launch_bounds__(256)
bucket_kernel(const float* __restrict__ pred, const float* __restrict__ targ)
{
    __shared__ int hist[256];            // S=200 padded to 256
    __shared__ int scanA[256], scanB[256];
    __shared__ int start[256], cur[256];
    const int c = blockIdx.x, b = blockIdx.y, tid = threadIdx.x;
    const float* src = (c == 0 ? pred : targ) + (size_t)b * N * 3;

    if (c == 0 && b == 0 && tid < 4) g_acc[tid] = 0.f;

    hist[tid] = 0;
    cur[tid]  = 0;
    __syncthreads();
    for (int i = tid; i < N; i += 256) {
        const float z = src[i * 3 + 2];
        const int s = min(max((int)((z - ZLO) * INVW), 0), S - 1);
        atomicAdd(&hist[s], 1);
    }
    __syncthreads();

    // exclusive scan over 256 entries (8 Hillis-Steele steps)
    const int v = hist[tid];
    scanA[tid] = v;
    __syncthreads();
    int* sA = scanA; int* sB = scanB;
#pragma unroll
    for (int off = 1; off < 256; off <<= 1) {
        sB[tid] = sA[tid] + ((tid >= off) ? sA[tid - off] : 0);
        int* t = sA; sA = sB; sB = t;
        __syncthreads();
    }
    start[tid] = sA[tid] - v;            // exclusive prefix
    __syncthreads();

    for (int i = tid; i < N; i += 256) {
        const float x = src[i * 3 + 0], y = src[i * 3 + 1], z = src[i * 3 + 2];
        const int s = min(max((int)((z - ZLO) * INVW), 0), S - 1);
        const int pos = start[s] + atomicAdd(&cur[s], 1);
        g_pts[c][b][pos] = make_float4(-2.f * x, -2.f * y, -2.f * z,
                                       x * x + y * y + z * z);
    }
    __syncthreads();

    // exact chunk z ranges: 8 warps x 4 chunks, 4 points per lane (CSZ=128)
    const int w = tid >> 5, lane = tid & 31;
    for (int q = 0; q < 4; q++) {
        const int ch = w * 4 + q;
        float zmn = CUDART_INF_F, zmx = -CUDART_INF_F;
#pragma unroll
        for (int i = 0; i < CSZ / 32; i++) {
            const float z = -0.5f * g_pts[c][b][ch * CSZ + lane + 32 * i].z;
            zmn = fminf(zmn, z);
            zmx = fmaxf(zmx, z);
        }
#pragma unroll
        for (int o = 16; o > 0; o >>= 1) {
            zmn = fminf(zmn, __shfl_down_sync(0xffffffffu, zmn, o));
            zmx = fmaxf(zmx, __shfl_down_sync(0xffffffffu, zmx, o));
        }
        if (lane == 0) g_cz[c][b][ch] = make_float2(zmn, zmx);
    }
}

// ---------------------------------------------------------------------------
// seed: per 128-query group, dense scan of 256 index-adjacent (z-near)
// targets -> exact per-query upper bound, stored to g_best (float bits);
// per-group UB^2 = max; unc partial sum (pass 0 only).
// ---------------------------------------------------------------------------
__global__ void __launch_bounds__(GSZ)
seed_kernel(const float* __restrict__ unc)
{
    __shared__ float4 st[SEEDW];
    __shared__ float  smax[GSZ / 32];

    const int g = blockIdx.x, b = blockIdx.y, pass = blockIdx.z;
    const int tid = threadIdx.x, lane = tid & 31, w = tid >> 5;
    const int qc = pass, tc = 1 - pass;
    const int i0 = g * GSZ;
    const int wlo = min(max(i0 - 64, 0), N - SEEDW);

    st[tid]       = g_pts[tc][b][wlo + tid];
    st[tid + GSZ] = g_pts[tc][b][wlo + tid + GSZ];

    const float4 Q  = g_pts[qc][b][i0 + tid];
    const float qx  = -0.5f * Q.x, qy = -0.5f * Q.y, qz = -0.5f * Q.z;
    const float qn2 = Q.w;
    __syncthreads();

    float b0 = CUDART_INF_F, b1 = CUDART_INF_F;
#pragma unroll 4
    for (int j = 0; j < SEEDW; j += 2) {
        const float4 t0 = st[j], t1 = st[j + 1];
        float d0 = fmaf(qz, t0.z, t0.w);
        float d1 = fmaf(qz, t1.z, t1.w);
        d0 = fmaf(qy, t0.y, d0);  d1 = fmaf(qy, t1.y, d1);
        d0 = fmaf(qx, t0.x, d0);  d1 = fmaf(qx, t1.x, d1);
        b0 = fminf(b0, d0);       b1 = fminf(b1, d1);
    }
    const float d2 = fmaxf(qn2 + fminf(b0, b1), 0.f);   // >=0 squared dist

    g_best[pass][b][i0 + tid] = __float_as_uint(d2);

    // group UB^2 = max over 128 queries
    float mx = d2;
#pragma unroll
    for (int o = 16; o > 0; o >>= 1)
        mx = fmaxf(mx, __shfl_down_sync(0xffffffffu, mx, o));
    if (lane == 0) smax[w] = mx;
    __syncthreads();
    if (tid == 0)
        g_ub2[pass][b][g] = fmaxf(fmaxf(smax[0], smax[1]),
                                  fmaxf(smax[2], smax[3]));

    if (pass == 0) {                             // unc sum (order-free)
        float u = unc[b * N + i0 + tid];
#pragma unroll
        for (int o = 16; o > 0; o >>= 1)
            u += __shfl_down_sync(0xffffffffu, u, o);
        if (lane == 0) atomicAdd(&g_acc[3], u);
    }
}

// ---------------------------------------------------------------------------
// main: dense shape (32 chunks x 8 tiles x 2B CTAs, 128 thr, R=4) with
// per-WARP chunk skip (gap^2 >= group UB^2). Survivors run the proven dense
// smem loop; result merged via atomicMin on float bits (>=0 => order-safe).
// Fused ticket reduce + finalize.
// ---------------------------------------------------------------------------
__global__ void __launch_bounds__(THREADS)
main_kernel(float* __restrict__ out)
{
    __shared__ float4   sc[CSZ];
    __shared__ int      s_skip;
    __shared__ unsigned s_ticket;
    __shared__ float    red[3][THREADS / 32];

    const int tid  = threadIdx.x, lane = tid & 31, w = tid >> 5;
    const int split = blockIdx.x, ntile = blockIdx.y, zz = blockIdx.z;
    const int b = zz & (B - 1), pass = zz >> 3;
    const int tc = 1 - pass;
    const int group = ntile * 4 + w;
    const int qbase = ntile * TN + w * GSZ + lane;

    const float4* __restrict__ T = g_pts[tc][b];

    if (tid == 0) s_skip = 0;

    float px[R], py[R], pz[R], pn2[R], r[R];
    float zmn = CUDART_INF_F, zmx = -CUDART_INF_F;
#pragma unroll
    for (int j = 0; j < R; j++) {
        const float4 Q = g_pts[pass][b][qbase + 32 * j];
        px[j] = -0.5f * Q.x; py[j] = -0.5f * Q.y; pz[j] = -0.5f * Q.z;
        pn2[j] = Q.w;  r[j] = CUDART_INF_F;
        zmn = fminf(zmn, pz[j]);  zmx = fmaxf(zmx, pz[j]);
    }
#pragma unroll
    for (int o = 16; o > 0; o >>= 1) {           // warp z-range (all lanes)
        zmn = fminf(zmn, __shfl_xor_sync(0xffffffffu, zmn, o));
        zmx = fmaxf(zmx, __shfl_xor_sync(0xffffffffu, zmx, o));
    }

    const float2 cz  = g_cz[tc][b][split];
    const float  gap = fmaxf(fmaxf(cz.x - zmx, zmn - cz.y), 0.f);
    const bool   skip = (gap * gap >= g_ub2[pass][b][group]);

    __syncthreads();
    if (lane == 0 && skip) atomicAdd(&s_skip, 1);
    __syncthreads();

    if (s_skip < 4) {                            // some warp needs this chunk
        sc[tid] = T[split * CSZ + tid];          // CSZ == THREADS
        __syncthreads();

        if (!skip) {
#pragma unroll 4
            for (int k = 0; k < CSZ; k++) {
                const float4 v = sc[k];
#pragma unroll
                for (int j = 0; j < R; j++) {
                    float d = fmaf(pz[j], v.z, v.w);
                    d = fmaf(py[j], v.y, d);
                    d = fmaf(px[j], v.x, d);
                    r[j] = fminf(r[j], d);
                }
            }
            unsigned* o = &g_best[pass][b][0];
#pragma unroll
            for (int j = 0; j < R; j++) {
                const float d2 = fmaxf(pn2[j] + r[j], 0.f);
                atomicMin(&o[qbase + 32 * j], __float_as_uint(d2));
            }
        }
    }

    // ---- ticket: last REDUCERS finishers reduce + finalize ----
    __threadfence();
    __syncthreads();
    if (tid == 0) s_ticket = atomicAdd(&g_count, 1u);
    __syncthreads();
    const unsigned my = s_ticket;
    if (my < (unsigned)(TOTALB - REDUCERS)) return;

    if (tid == 0) {
        while (*((volatile unsigned*)&g_count) < (unsigned)TOTALB)
            __nanosleep(64);
    }
    __syncthreads();
    __threadfence();

    const int rid  = (int)my - (TOTALB - REDUCERS);
    const int base = rid * PTS_PER_RED;

    float s_row = 0.f, s_sqrt = 0.f, s_col = 0.f;
#pragma unroll
    for (int it = 0; it < PTS_PER_RED / THREADS; it++) {
        const int idx = base + it * THREADS + tid;
        const int bb = idx >> 12, nn = idx & (N - 1);

        const float m = __uint_as_float(g_best[0][bb][nn]);
        s_row  += m;
        s_sqrt += sqrtf(m);
        s_col  += __uint_as_float(g_best[1][bb][nn]);
    }
#pragma unroll
    for (int o = 16; o > 0; o >>= 1) {
        s_row  += __shfl_down_sync(0xffffffffu, s_row,  o);
        s_sqrt += __shfl_down_sync(0xffffffffu, s_sqrt, o);
        s_col  += __shfl_down_sync(0xffffffffu, s_col,  o);
    }
    if (lane == 0) {
        red[0][w] = s_row; red[1][w] = s_sqrt; red[2][w] = s_col;
    }
    __syncthreads();
    if (tid == 0) {
        float a0 = 0.f, a1 = 0.f, a2 = 0.f;
#pragma unroll
        for (int ww = 0; ww < THREADS / 32; ww++) {
            a0 += red[0][ww]; a1 += red[1][ww]; a2 += red[2][ww];
        }
        atomicAdd(&g_acc[0], a0);
        atomicAdd(&g_acc[1], a1);
        atomicAdd(&g_acc[2], a2);

        __threadfence();
        const unsigned done = atomicAdd(&g_count2, 1u);
        if (done == (unsigned)(REDUCERS - 1)) {
            const float inv = 1.0f / (float)(B * N);
            const float chamfer = (g_acc[0] + g_acc[2]) * inv;
            const float emd     = g_acc[1] * inv;
            const float u       = g_acc[3] * inv;
            out[0] = chamfer * 1.0f + emd * 0.5f + u * 0.01f;
            g_count  = 0;                       // reset for graph replay
            g_count2 = 0;
        }
    }
}

// ---------------------------------------------------------------------------
extern "C" void kernel_launch(void* const* d_in, const int* in_sizes, int n_in,
                              void* d_out, int out_size)
{
    const float* pred = (const float*)d_in[0];   // [B, N, 3]
    const float* targ = (const float*)d_in[1];   // [B, M, 3]
    const float* unc  = (const float*)d_in[2];   // [B, N]
    float* out = (float*)d_out;

    dim3 bgrid(2, B);                            // 16 blocks
    bucket_kernel<<<bgrid, 256>>>(pred, targ);

    dim3 sgrid(GROUPS, B, 2);                    // 512 blocks x 128
    seed_kernel<<<sgrid, GSZ>>>(unc);

    dim3 mgrid(SPLIT, NTILES, 2 * B);            // 4096 blocks x 128
    main_kernel<<<mgrid, THREADS>>>(out);
}

// round 15
// speedup vs baseline: 4.0611x; 1.0241x over previous
#include <cuda_runtime.h>
#include <math_constants.h>

constexpr int B = 8;
constexpr int N = 4096;              // == M

// z-strip sort grid
constexpr int   S    = 200;
constexpr float ZLO  = -5.0f;
constexpr float INVW = 20.0f;

constexpr int SPLIT  = 32;           // target chunks
constexpr int CSZ    = N / SPLIT;    // 128 targets per chunk
constexpr int GROUPS = 32;           // query groups per (pass,b)  (== SPLIT)
constexpr int GSZ    = N / GROUPS;   // 128 queries per group (== CSZ)
constexpr int SEEDW  = 256;          // seed window (targets) per group

constexpr int THREADS = 128;         // main block (4 warps)
constexpr int R       = 4;
constexpr int TN      = THREADS * R; // 512 queries per tile
constexpr int NTILES  = N / TN;      // 8

constexpr int SORTB  = 8;            // sort blocks per (c,b)
constexpr int SLICE  = N / SORTB;    // 512 points per sort block

constexpr int TOTALB      = SPLIT * NTILES * 2 * B;  // 4096 main CTAs
constexpr int REDUCERS    = 128;
constexpr int PTS_PER_RED = (B * N) / REDUCERS;      // 256
constexpr int NHIST       = 2 * B * S;               // 3200

// Scratch (no device allocations allowed; zero-initialized at load)
__device__ float4   g_pts[2][B][N];        // (-2x,-2y,-2z, x2+y2+z2), z-sorted
__device__ float2   g_cz[2][B][SPLIT];     // chunk (zmin, zmax)
__device__ unsigned g_best[2][B][N];       // best d2 as uint bits (>=0 floats)
__device__ float    g_ub2[2][B][GROUPS];   // per-group NN upper bound^2
__device__ unsigned g_hist[2][B][S];       // strip histogram
__device__ unsigned g_cur[2][B][S];        // scatter cursors
__device__ float    g_acc[4];              // rowsum, sqrtsum, colsum, uncsum
__device__ unsigned g_count  = 0;          // main-CTA ticket
__device__ unsigned g_count2 = 0;          // reducer ticket

// ---------------------------------------------------------------------------
// hist: grid (2, B, SORTB) x 256. Global-atomic strip histogram.
// ---------------------------------------------------------------------------
__global__ void __launch_bounds__(256)
hist_kernel(const float* __restrict__ pred, const float* __restrict__ targ)
{
    const int c = blockIdx.x, b = blockIdx.y, blk = blockIdx.z;
    const int tid = threadIdx.x;
    const float* src = (c == 0 ? pred : targ) + (size_t)b * N * 3;

    if (c == 0 && b == 0 && blk == 0 && tid < 4) g_acc[tid] = 0.f;

    const int i0 = blk * SLICE;
    for (int i = i0 + tid; i < i0 + SLICE; i += 256) {
        const float z = src[i * 3 + 2];
        const int s = min(max((int)((z - ZLO) * INVW), 0), S - 1);
        atomicAdd(&g_hist[c][b][s], 1u);
    }
}

// ---------------------------------------------------------------------------
// scatter: grid (2, B, SORTB) x 256. Each block re-derives the exclusive
// scan of its (c,b) histogram locally (cheap), then scatters its slice via
// global cursors. Within-strip order is nondeterministic — harmless (mins
// and chunk bounds are order-independent).
// ---------------------------------------------------------------------------
__global__ void __launch_bounds__(256)
scatter_kernel(const float* __restrict__ pred, const float* __restrict__ targ)
{
    __shared__ int scanA[256], scanB[256], start[256];
    const int c = blockIdx.x, b = blockIdx.y, blk = blockIdx.z;
    const int tid = threadIdx.x;
    const float* src = (c == 0 ? pred : targ) + (size_t)b * N * 3;

    const int v = (tid < S) ? (int)g_hist[c][b][tid] : 0;
    scanA[tid] = v;
    __syncthreads();
    int* sA = scanA; int* sB = scanB;
#pragma unroll
    for (int off = 1; off < 256; off <<= 1) {
        sB[tid] = sA[tid] + ((tid >= off) ? sA[tid - off] : 0);
        int* t = sA; sA = sB; sB = t;
        __syncthreads();
    }
    start[tid] = sA[tid] - v;            // exclusive prefix
    __syncthreads();

    const int i0 = blk * SLICE;
    for (int i = i0 + tid; i < i0 + SLICE; i += 256) {
        const float x = src[i * 3 + 0], y = src[i * 3 + 1], z = src[i * 3 + 2];
        const int s = min(max((int)((z - ZLO) * INVW), 0), S - 1);
        const int pos = start[s] + (int)atomicAdd(&g_cur[c][b][s], 1u);
        g_pts[c][b][pos] = make_float4(-2.f * x, -2.f * y, -2.f * z,
                                       x * x + y * y + z * z);
    }
}

// ---------------------------------------------------------------------------
// seed: per 128-query group, dense scan of 256 index-adjacent (z-near)
// targets -> exact per-query upper bound into g_best; per-group UB^2 = max;
// chunk z-bounds for chunk g of cloud tc; unc partial sum (pass 0 only).
// ---------------------------------------------------------------------------
__global__ void __launch_bounds__(GSZ)
seed_kernel(const float* __restrict__ unc)
{
    __shared__ float4 st[SEEDW];
    __shared__ float  smax[GSZ / 32];
    __shared__ float  szmn[GSZ / 32], szmx[GSZ / 32];

    const int g = blockIdx.x, b = blockIdx.y, pass = blockIdx.z;
    const int tid = threadIdx.x, lane = tid & 31, w = tid >> 5;
    const int qc = pass, tc = 1 - pass;
    const int i0 = g * GSZ;
    const int wlo = min(max(i0 - 64, 0), N - SEEDW);

    st[tid]       = g_pts[tc][b][wlo + tid];
    st[tid + GSZ] = g_pts[tc][b][wlo + tid + GSZ];

    const float4 Q  = g_pts[qc][b][i0 + tid];
    const float qx  = -0.5f * Q.x, qy = -0.5f * Q.y, qz = -0.5f * Q.z;
    const float qn2 = Q.w;

    // chunk z-bounds for chunk g of cloud tc (CSZ == GSZ == 128)
    {
        float z = -0.5f * g_pts[tc][b][g * CSZ + tid].z;
        float zmn = z, zmx = z;
#pragma unroll
        for (int o = 16; o > 0; o >>= 1) {
            zmn = fminf(zmn, __shfl_xor_sync(0xffffffffu, zmn, o));
            zmx = fmaxf(zmx, __shfl_xor_sync(0xffffffffu, zmx, o));
        }
        if (lane == 0) { szmn[w] = zmn; szmx[w] = zmx; }
    }
    __syncthreads();
    if (tid == 0) {
        const float zmn = fminf(fminf(szmn[0], szmn[1]), fminf(szmn[2], szmn[3]));
        const float zmx = fmaxf(fmaxf(szmx[0], szmx[1]), fmaxf(szmx[2], szmx[3]));
        g_cz[tc][b][g] = make_float2(zmn, zmx);
    }

    float b0 = CUDART_INF_F, b1 = CUDART_INF_F;
#pragma unroll 4
    for (int j = 0; j < SEEDW; j += 2) {
        const float4 t0 = st[j], t1 = st[j + 1];
        float d0 = fmaf(qz, t0.z, t0.w);
        float d1 = fmaf(qz, t1.z, t1.w);
        d0 = fmaf(qy, t0.y, d0);  d1 = fmaf(qy, t1.y, d1);
        d0 = fmaf(qx, t0.x, d0);  d1 = fmaf(qx, t1.x, d1);
        b0 = fminf(b0, d0);       b1 = fminf(b1, d1);
    }
    const float d2 = fmaxf(qn2 + fminf(b0, b1), 0.f);   // >=0 squared dist

    g_best[pass][b][i0 + tid] = __float_as_uint(d2);

    // group UB^2 = max over 128 queries
    float mx = d2;
#pragma unroll
    for (int o = 16; o > 0; o >>= 1)
        mx = fmaxf(mx, __shfl_down_sync(0xffffffffu, mx, o));
    if (lane == 0) smax[w] = mx;
    __syncthreads();
    if (tid == 0)
        g_ub2[pass][b][g] = fmaxf(fmaxf(smax[0], smax[1]),
                                  fmaxf(smax[2], smax[3]));

    if (pass == 0) {                             // unc sum (order-free)
        float u = unc[b * N + i0 + tid];
#pragma unroll
        for (int o = 16; o > 0; o >>= 1)
            u += __shfl_down_sync(0xffffffffu, u, o);
        if (lane == 0) atomicAdd(&g_acc[3], u);
    }
}

// ---------------------------------------------------------------------------
// main: dense shape (32 chunks x 8 tiles x 2B CTAs, 128 thr, R=4) with
// per-WARP chunk skip (gap^2 >= group UB^2). Survivors run the dense smem
// loop; merged via atomicMin on float bits. zz==0 blocks also reset the
// sort counters for the next graph replay. Fused ticket reduce + finalize.
// ---------------------------------------------------------------------------
__global__ void __launch_bounds__(THREADS)
main_kernel(float* __restrict__ out)
{
    __shared__ float4   sc[CSZ];
    __shared__ int      s_skip;
    __shared__ unsigned s_ticket;
    __shared__ float    red[3][THREADS / 32];

    const int tid  = threadIdx.x, lane = tid & 31, w = tid >> 5;
    const int split = blockIdx.x, ntile = blockIdx.y, zz = blockIdx.z;
    const int b = zz & (B - 1), pass = zz >> 3;
    const int tc = 1 - pass;
    const int group = ntile * 4 + w;
    const int qbase = ntile * TN + w * GSZ + lane;

    const float4* __restrict__ T = g_pts[tc][b];

    if (tid == 0) s_skip = 0;

    // reset sort scratch for next graph replay (nothing reads it after scatter)
    if (zz == 0) {
        const int flat = (split * NTILES + ntile) * THREADS + tid;
        if (flat < NHIST) {
            (&g_hist[0][0][0])[flat] = 0u;
            (&g_cur[0][0][0])[flat]  = 0u;
        }
    }

    float px[R], py[R], pz[R], pn2[R], r[R];
    float zmn = CUDART_INF_F, zmx = -CUDART_INF_F;
#pragma unroll
    for (int j = 0; j < R; j++) {
        const float4 Q = g_pts[pass][b][qbase + 32 * j];
        px[j] = -0.5f * Q.x; py[j] = -0.5f * Q.y; pz[j] = -0.5f * Q.z;
        pn2[j] = Q.w;  r[j] = CUDART_INF_F;
        zmn = fminf(zmn, pz[j]);  zmx = fmaxf(zmx, pz[j]);
    }
#pragma unroll
    for (int o = 16; o > 0; o >>= 1) {           // warp z-range (all lanes)
        zmn = fminf(zmn, __shfl_xor_sync(0xffffffffu, zmn, o));
        zmx = fmaxf(zmx, __shfl_xor_sync(0xffffffffu, zmx, o));
    }

    const float2 cz  = g_cz[tc][b][split];
    const float  gap = fmaxf(fmaxf(cz.x - zmx, zmn - cz.y), 0.f);
    const bool   skip = (gap * gap >= g_ub2[pass][b][group]);

    __syncthreads();
    if (lane == 0 && skip) atomicAdd(&s_skip, 1);
    __syncthreads();

    if (s_skip < 4) {                            // some warp needs this chunk
        sc[tid] = T[split * CSZ + tid];          // CSZ == THREADS
        __syncthreads();

        if (!skip) {
#pragma unroll 4
            for (int k = 0; k < CSZ; k++) {
                const float4 v = sc[k];
#pragma unroll
                for (int j = 0; j < R; j++) {
                    float d = fmaf(pz[j], v.z, v.w);
                    d = fmaf(py[j], v.y, d);
                    d = fmaf(px[j], v.x, d);
                    r[j] = fminf(r[j], d);
                }
            }
            unsigned* o = &g_best[pass][b][0];
#pragma unroll
            for (int j = 0; j < R; j++) {
                const float d2 = fmaxf(pn2[j] + r[j], 0.f);
                atomicMin(&o[qbase + 32 * j], __float_as_uint(d2));
            }
        }
    }

    // ---- ticket: last REDUCERS finishers reduce + finalize ----
    __threadfence();
    __syncthreads();
    if (tid == 0) s_ticket = atomicAdd(&g_count, 1u);
    __syncthreads();
    const unsigned my = s_ticket;
    if (my < (unsigned)(TOTALB - REDUCERS)) return;

    if (tid == 0) {
        while (*((volatile unsigned*)&g_count) < (unsigned)TOTALB)
            __nanosleep(64);
    }
    __syncthreads();
    __threadfence();

    const int rid  = (int)my - (TOTALB - REDUCERS);
    const int base = rid * PTS_PER_RED;

    float s_row = 0.f, s_sqrt = 0.f, s_col = 0.f;
#pragma unroll
    for (int it = 0; it < PTS_PER_RED / THREADS; it++) {
        const int idx = base + it * THREADS + tid;
        const int bb = idx >> 12, nn = idx & (N - 1);

        const float m = __uint_as_float(g_best[0][bb][nn]);
        s_row  += m;
        s_sqrt += sqrtf(m);
        s_col  += __uint_as_float(g_best[1][bb][nn]);
    }
#pragma unroll
    for (int o = 16; o > 0; o >>= 1) {
        s_row  += __shfl_down_sync(0xffffffffu, s_row,  o);
        s_sqrt += __shfl_down_sync(0xffffffffu, s_sqrt, o);
        s_col  += __shfl_down_sync(0xffffffffu, s_col,  o);
    }
    if (lane == 0) {
        red[0][w] = s_row; red[1][w] = s_sqrt; red[2][w] = s_col;
    }
    __syncthreads();
    if (tid == 0) {
        float a0 = 0.f, a1 = 0.f, a2 = 0.f;
#pragma unroll
        for (int ww = 0; ww < THREADS / 32; ww++) {
            a0 += red[0][ww]; a1 += red[1][ww]; a2 += red[2][ww];
        }
        atomicAdd(&g_acc[0], a0);
        atomicAdd(&g_acc[1], a1);
        atomicAdd(&g_acc[2], a2);

        __threadfence();
        const unsigned done = atomicAdd(&g_count2, 1u);
        if (done == (unsigned)(REDUCERS - 1)) {
            const float inv = 1.0f / (float)(B * N);
            const float chamfer = (g_acc[0] + g_acc[2]) * inv;
            const float emd     = g_acc[1] * inv;
            const float u       = g_acc[3] * inv;
            out[0] = chamfer * 1.0f + emd * 0.5f + u * 0.01f;
            g_count  = 0;                       // reset for graph replay
            g_count2 = 0;
        }
    }
}

// ---------------------------------------------------------------------------
extern "C" void kernel_launch(void* const* d_in, const int* in_sizes, int n_in,
                              void* d_out, int out_size)
{
    const float* pred = (const float*)d_in[0];   // [B, N, 3]
    const float* targ = (const float*)d_in[1];   // [B, M, 3]
    const float* unc  = (const float*)d_in[2];   // [B, N]
    float* out = (float*)d_out;

    dim3 hgrid(2, B, SORTB);                     // 128 blocks
    hist_kernel<<<hgrid, 256>>>(pred, targ);
    scatter_kernel<<<hgrid, 256>>>(pred, targ);

    dim3 sgrid(GROUPS, B, 2);                    // 512 blocks x 128
    seed_kernel<<<sgrid, GSZ>>>(unc);

    dim3 mgrid(SPLIT, NTILES, 2 * B);            // 4096 blocks x 128
    main_kernel<<<mgrid, THREADS>>>(out);
}